// round 15
// baseline (speedup 1.0000x reference)
#include <cuda_runtime.h>
#include <stdint.h>

// Problem constants (fixed by the benchmark's setup_inputs)
namespace {
constexpr int BSZ     = 256;
constexpr int NMAX    = 8192;
constexpr int ENS     = 4;
constexpr int REPEAT  = 2;
constexpr int KSEL    = 32;
constexpr int ROWS    = REPEAT * BSZ * ENS;   // 2048
constexpr int THREADS = 1024;
constexpr int EPT     = NMAX / THREADS;       // 8 elements per thread
constexpr float EPSF  = 1.17549435e-38f;      // np.float32 tiny
// State pre-scaled into log2 domain: y2 = f * (10/ln2), tau = 0.1.
constexpr float SCALE = 14.426950408889634f;  // 10 / ln(2)
// Elements > 30 (log2) below the current max contribute < 2^-30: exact-skip
// class already validated (rel_err 0.0 in rounds 13-14).
constexpr float HOT_GUARD  = 30.0f;
// Initial/expansion candidate threshold margin below the current max.
constexpr float CAND_DELTA = 95.0f;
constexpr int   CAP        = 4096;            // candidate capacity

// dynamic smem layout (bytes)
constexpr int SMEM_DYN = NMAX * 4      // y2all
                       + CAP * 4       // cy2
                       + CAP * 4       // ckhot
                       + 64            // ctrl
                       + CAP * 2       // cidx
                       + NMAX;         // flag bytes
}

__device__ __forceinline__ float ex2_approx(float x) {
  float r; asm("ex2.approx.ftz.f32 %0, %1;" : "=f"(r) : "f"(x)); return r;
}
__device__ __forceinline__ float lg2_approx(float x) {
  float r; asm("lg2.approx.ftz.f32 %0, %1;" : "=f"(r) : "f"(x)); return r;
}
__device__ __forceinline__ float rcp_approx(float x) {
  float r; asm("rcp.approx.ftz.f32 %0, %1;" : "=f"(r) : "f"(x)); return r;
}

// order-preserving float<->uint mapping (REDUX-based float max)
__device__ __forceinline__ unsigned ford(float f) {
  unsigned u = __float_as_uint(f);
  return u ^ ((unsigned)((int)u >> 31) | 0x80000000u);
}
__device__ __forceinline__ float funord(unsigned e) {
  return __uint_as_float(e ^ ((~(unsigned)((int)e >> 31)) | 0x80000000u));
}

// JAX threefry2x32 with key = (0, 42)  (jax.random.key(42))
__device__ __forceinline__ void threefry2x32_0_42(uint32_t c0, uint32_t c1,
                                                  uint32_t& o0, uint32_t& o1) {
  const uint32_t k0 = 0u;
  const uint32_t k1 = 42u;
  const uint32_t k2 = 0x1BD11BDAu ^ k0 ^ k1;
  uint32_t x0 = c0 + k0;
  uint32_t x1 = c1 + k1;
#define TFR(r) { x0 += x1; x1 = __funnelshift_l(x1, x1, (r)); x1 ^= x0; }
  TFR(13) TFR(15) TFR(26) TFR(6)   x0 += k1; x1 += k2 + 1u;
  TFR(17) TFR(29) TFR(16) TFR(24)  x0 += k2; x1 += k0 + 2u;
  TFR(13) TFR(15) TFR(26) TFR(6)   x0 += k0; x1 += k1 + 3u;
  TFR(17) TFR(29) TFR(16) TFR(24)  x0 += k1; x1 += k2 + 4u;
  TFR(13) TFR(15) TFR(26) TFR(6)   x0 += k2; x1 += k0 + 5u;
#undef TFR
  o0 = x0; o1 = x1;
}

__global__ void __launch_bounds__(THREADS, 1)
gumbel_topk_kernel(const float* __restrict__ scores, float* __restrict__ out) {
  // small static scratch (block reductions + fallback machinery)
  __shared__ unsigned shm[32];
  __shared__ float    shs[32];
  __shared__ int      shi[32];
  __shared__ unsigned long long shk[33];

  extern __shared__ char dsm[];
  float* y2all = (float*)dsm;                          // [NMAX]
  float* cy2   = y2all + NMAX;                         // [CAP]
  float* ckhot = cy2 + CAP;                            // [CAP]
  int*   ctrl  = (int*)(ckhot + CAP);                  // [16]
  unsigned short* cidx = (unsigned short*)(ctrl + 16); // [CAP]
  unsigned char*  flag = (unsigned char*)(cidx + CAP); // [NMAX]

  const int row  = blockIdx.x;
  const int t    = threadIdx.x;
  const int w    = t >> 5;
  const int lane = t & 31;
  const unsigned lmask_lt = (lane == 0) ? 0u : (0xFFFFFFFFu >> (32 - lane));
  const int rep  = row >> 10;
  const int q    = row & 1023;
  const int b    = q >> 2;
  const int e    = q & 3;

  const float* srow = scores + ((size_t)b * NMAX) * ENS + e;
  float* orow = out + (((size_t)(rep * BSZ + b)) * NMAX) * ENS + e;

  float y2[EPT], khot[EPT];

  // ---- init: gumbel noise (JAX partitionable threefry) + scores ----
#pragma unroll
  for (int i = 0; i < EPT; i++) {
    const int n = t + i * THREADS;
    const unsigned j = (unsigned)row * (unsigned)NMAX + (unsigned)n;
    uint32_t r0, r1;
    threefry2x32_0_42(0u, j, r0, r1);
    const uint32_t bits = r0 ^ r1;
    float u = __uint_as_float((bits >> 9) | 0x3F800000u) - 1.0f;
    u = fmaxf(u + EPSF, EPSF);
    const float g = -logf(-logf(u));        // accurate path for init
    y2[i] = (srow[(size_t)n * ENS] + g) * SCALE;
    khot[i] = 0.0f;
    y2all[n] = y2[i];
    orow[(size_t)n * ENS] = 0.0f;           // clears poison
  }

  // ---- block max m0 ----
  {
    float lm = y2[0];
#pragma unroll
    for (int i = 1; i < EPT; i++) lm = fmaxf(lm, y2[i]);
    const unsigned o = __reduce_max_sync(0xFFFFFFFFu, ford(lm));
    if (lane == 0) shm[w] = o;
  }
  __syncthreads();
  const float m0 = funord(__reduce_max_sync(0xFFFFFFFFu, shm[lane]));
  const float T0 = m0 - CAND_DELTA;

  // ---- deterministic compaction of candidates {y2 >= T0} ----
  unsigned cmask[EPT];
  int c_w = 0;
#pragma unroll
  for (int i = 0; i < EPT; i++) {
    const bool p = (y2[i] >= T0);
    cmask[i] = __ballot_sync(0xFFFFFFFFu, p);
    c_w += __popc(cmask[i]);
    flag[t + i * THREADS] = p ? 1 : 0;
  }
  if (lane == 0) shi[w] = c_w;
  __syncthreads();
  if (t < 32) {                              // warp 0: exclusive scan of warp counts
    const int v = shi[t];
    int incl = v;
#pragma unroll
    for (int o = 1; o < 32; o <<= 1) {
      const int u2 = __shfl_up_sync(0xFFFFFFFFu, incl, o);
      if (lane >= o) incl += u2;
    }
    shi[t] = incl - v;
    if (t == 31) ctrl[0] = incl;             // total count
  }
  __syncthreads();
  {
    int base = shi[w];
#pragma unroll
    for (int i = 0; i < EPT; i++) {
      if (y2[i] >= T0) {
        const int r = base + __popc(cmask[i] & lmask_lt);
        if (r < CAP) {
          cidx[r] = (unsigned short)(t + i * THREADS);
          cy2[r] = y2[i];
          ckhot[r] = 0.0f;
        }
      }
      base += __popc(cmask[i]);
    }
  }
  __syncthreads();

  // ---- phase 1: single-warp dynamics over candidates ----
  if (w == 0) {
    int cnt = ctrl[0];
    int ok = (cnt <= CAP) ? 1 : 0;
    float T = T0;

    if (ok) {
      for (int it = 0; it < KSEL; it++) {
        // candidate max
        float lm = -3.4e38f;
        for (int c = lane; c < cnt; c += 32) lm = fmaxf(lm, cy2[c]);
        const float m2 = funord(__reduce_max_sync(0xFFFFFFFFu, ford(lm)));

        // adaptive coverage: everything >= m2-HOT_GUARD must be a candidate
        if (m2 - HOT_GUARD < T) {
          const float Tn = m2 - CAND_DELTA;
          for (int nb = lane; nb < NMAX; nb += 32) {
            const bool p = (!flag[nb]) && (y2all[nb] >= Tn);
            const unsigned msk = __ballot_sync(0xFFFFFFFFu, p);
            const int add = __popc(msk);
            if (cnt + add > CAP) { ok = 0; break; }
            if (p) {
              const int r = cnt + __popc(msk & lmask_lt);
              cidx[r] = (unsigned short)nb;
              cy2[r] = y2all[nb];
              ckhot[r] = 0.0f;
              flag[nb] = 1;
            }
            cnt += add;
          }
          T = Tn;
          if (!ok) break;
        }

        // s = sum exp2(y2 - m2)
        float ls = 0.0f;
        for (int c = lane; c < cnt; c += 32) ls += ex2_approx(cy2[c] - m2);
#pragma unroll
        for (int o = 16; o; o >>= 1) ls += __shfl_xor_sync(0xFFFFFFFFu, ls, o);
        const float rs = rcp_approx(ls);

        // update khot and knock down
        for (int c = lane; c < cnt; c += 32) {
          const float y = cy2[c];
          const float ev = ex2_approx(y - m2);
          if (ev != 0.0f) {
            const float oh = ev * rs;
            ckhot[c] += oh;
            const float mk = 1.0f - oh;
            if (mk < 1.0f)
              cy2[c] = y + 10.0f * lg2_approx(fmaxf(mk, EPSF));
          }
        }
      }
    }

    // ---- top-32 among candidates ----
    if (ok) {
      int pos = 0, hi = 0;
      unsigned long long myk = 0ull;
      for (int c = lane; c < cnt; c += 32) {
        const float kh = ckhot[c];
        pos += (kh > 0.0f) ? 1 : 0;
        hi  += (kh > 0.5f) ? 1 : 0;
        const unsigned long long key =
            ((unsigned long long)(__float_as_uint(kh) | 0x80000000u) << 32)
            | (unsigned)(NMAX - 1 - cidx[c]);
        myk = (key > myk) ? key : myk;
      }
      pos = __reduce_add_sync(0xFFFFFFFFu, (unsigned)pos);
      hi  = __reduce_add_sync(0xFFFFFFFFu, (unsigned)hi);

      if (pos < KSEL) {
        ok = 0;                              // punt rare corner to fallback
      } else if (hi == KSEL) {
        // exactly 32 elements above 0.5: they ARE the top-32 (no ties possible)
        for (int c = lane; c < cnt; c += 32)
          if (ckhot[c] > 0.5f) orow[(size_t)cidx[c] * ENS] = 1.0f;
      } else {
        for (int sel = 0; sel < KSEL; sel++) {
          const unsigned mh = __reduce_max_sync(0xFFFFFFFFu, (unsigned)(myk >> 32));
          const unsigned ml = __reduce_max_sync(
              0xFFFFFFFFu, ((unsigned)(myk >> 32) == mh) ? (unsigned)myk : 0u);
          const unsigned long long win = ((unsigned long long)mh << 32) | ml;
          if (myk == win) {                  // winning lane
            const int n = NMAX - 1 - (int)ml;
            orow[(size_t)n * ENS] = 1.0f;
            unsigned long long nk = 0ull;
            for (int c = lane; c < cnt; c += 32) {
              if (cidx[c] == (unsigned short)n) ckhot[c] = -1.0f;
              const float kh = ckhot[c];
              const unsigned ord = (kh >= 0.0f)
                  ? (__float_as_uint(kh) | 0x80000000u) : 0u;
              const unsigned long long key =
                  ((unsigned long long)ord << 32)
                  | (unsigned)(NMAX - 1 - cidx[c]);
              nk = (key > nk) ? key : nk;
            }
            myk = nk;
          }
        }
      }
    }
    if (lane == 0) ctrl[1] = ok ? 0 : 1;
  }
  __syncthreads();
  if (ctrl[1] == 0) return;

  // ================= fallback: full-block path (round-14, known good) ========
  bool dirty = true;
  float m_w = 0.0f;
  for (int it = 0; it < KSEL; it++) {
    if (dirty) {
      float lm = y2[0];
#pragma unroll
      for (int i = 1; i < EPT; i++) lm = fmaxf(lm, y2[i]);
      const unsigned o = __reduce_max_sync(0xFFFFFFFFu, ford(lm));
      m_w = funord(o);
      if (lane == 0) shm[w] = o;
      dirty = false;
    }
    __syncthreads();
    const float m2 = funord(__reduce_max_sync(0xFFFFFFFFu, shm[lane]));
    const bool hot = (m_w >= m2 - HOT_GUARD);

    float ex[EPT];
    float s_w = 0.0f;
    if (hot) {
#pragma unroll
      for (int i = 0; i < EPT; i++) {
        const float ev = ex2_approx(y2[i] - m2);
        ex[i] = ev;
        s_w += ev;
      }
#pragma unroll
      for (int o = 16; o; o >>= 1) s_w += __shfl_xor_sync(0xFFFFFFFFu, s_w, o);
    }
    if (lane == 0) shs[w] = hot ? s_w : 0.0f;
    __syncthreads();

    if (hot) {
      float s = shs[lane];
#pragma unroll
      for (int o = 16; o; o >>= 1) s += __shfl_xor_sync(0xFFFFFFFFu, s, o);
      const float rs = rcp_approx(s);
      bool need = false;
#pragma unroll
      for (int i = 0; i < EPT; i++) {
        ex[i] *= rs;
        khot[i] += ex[i];
        need |= (1.0f - ex[i] < 1.0f);
      }
      if (__any_sync(0xFFFFFFFFu, need)) {
#pragma unroll
        for (int i = 0; i < EPT; i++) {
          const float mk = 1.0f - ex[i];
          if (mk < 1.0f)
            y2[i] += 10.0f * lg2_approx(fmaxf(mk, EPSF));
        }
        dirty = true;
      }
    }
  }

  // fallback top-k (poisoned output region may have stray 1s? no: phase-1 aborts
  // happen before any scatter, so orow still all zeros here)
  int cntp = 0;
#pragma unroll
  for (int i = 0; i < EPT; i++) cntp += (khot[i] > 0.5f) ? 1 : 0;
  cntp = __reduce_add_sync(0xFFFFFFFFu, (unsigned)cntp);
  if (lane == 0) shi[w] = cntp;
  __syncthreads();
  const int total = __reduce_add_sync(0xFFFFFFFFu, (unsigned)shi[lane]);
  if (total == KSEL) {
#pragma unroll
    for (int i = 0; i < EPT; i++)
      if (khot[i] > 0.5f) orow[(size_t)(t + i * THREADS) * ENS] = 1.0f;
    return;
  }

  unsigned long long myk = 0ull;
#pragma unroll
  for (int i = 0; i < EPT; i++) {
    const int n = t + i * THREADS;
    const unsigned ord = (khot[i] >= 0.0f)
        ? (__float_as_uint(khot[i]) | 0x80000000u) : 0u;
    const unsigned long long key =
        ((unsigned long long)ord << 32) | (unsigned)(NMAX - 1 - n);
    myk = (key > myk) ? key : myk;
  }
  for (int sel = 0; sel < KSEL; sel++) {
    unsigned long long lk = myk;
#pragma unroll
    for (int o = 16; o; o >>= 1) {
      const unsigned long long v = __shfl_xor_sync(0xFFFFFFFFu, lk, o);
      lk = (v > lk) ? v : lk;
    }
    if (lane == 0) shk[w] = lk;
    __syncthreads();
    if (t < 32) {
      unsigned long long v = shk[t];
#pragma unroll
      for (int o = 16; o; o >>= 1) {
        const unsigned long long x = __shfl_xor_sync(0xFFFFFFFFu, v, o);
        v = (x > v) ? x : v;
      }
      if (t == 0) shk[32] = v;
    }
    __syncthreads();
    const int n = NMAX - 1 - (int)(shk[32] & 0xFFFFFFFFull);
    if ((n & (THREADS - 1)) == t) {
      const int i = n >> 10;
#pragma unroll
      for (int ii = 0; ii < EPT; ii++)
        if (ii == i) khot[ii] = -1.0f;
      orow[(size_t)n * ENS] = 1.0f;
      unsigned long long nk = 0ull;
#pragma unroll
      for (int ii = 0; ii < EPT; ii++) {
        const int nn = t + ii * THREADS;
        const unsigned ord = (khot[ii] >= 0.0f)
            ? (__float_as_uint(khot[ii]) | 0x80000000u) : 0u;
        const unsigned long long key =
            ((unsigned long long)ord << 32) | (unsigned)(NMAX - 1 - nn);
        nk = (key > nk) ? key : nk;
      }
      myk = nk;
    }
  }
}

extern "C" void kernel_launch(void* const* d_in, const int* in_sizes, int n_in,
                              void* d_out, int out_size) {
  const float* scores = (const float*)d_in[0];
  float* out = (float*)d_out;
  cudaFuncSetAttribute(gumbel_topk_kernel,
                       cudaFuncAttributeMaxDynamicSharedMemorySize, SMEM_DYN);
  gumbel_topk_kernel<<<ROWS, THREADS, SMEM_DYN>>>(scores, out);
  (void)in_sizes; (void)n_in; (void)out_size;
}